// round 5
// baseline (speedup 1.0000x reference)
#include <cuda_runtime.h>
#include <cstdint>

#define B_ROWS 8192
#define C_ROWS 10000
#define D_DIM  512
#define ROW_BYTES   2048                 // 512 f32
#define ROWS_PER_CTA 8
#define GRID_CTAS (B_ROWS / ROWS_PER_CTA)  // 1024
#define THREADS 256                      // 8 warps, warp w <-> stage w

__device__ __forceinline__ uint32_t smem_u32(const void* p) {
    uint32_t a;
    asm("{ .reg .u64 t; cvta.to.shared.u64 t, %1; cvt.u32.u64 %0, t; }"
        : "=r"(a) : "l"(p));
    return a;
}

__device__ __forceinline__ void mbar_init(uint32_t mbar, uint32_t count) {
    asm volatile("mbarrier.init.shared.b64 [%0], %1;" :: "r"(mbar), "r"(count) : "memory");
}
__device__ __forceinline__ void mbar_expect_tx(uint32_t mbar, uint32_t bytes) {
    asm volatile("mbarrier.arrive.expect_tx.shared.b64 _, [%0], %1;"
                 :: "r"(mbar), "r"(bytes) : "memory");
}
__device__ __forceinline__ void bulk_g2s(uint32_t dst, const void* src,
                                         uint32_t bytes, uint32_t mbar) {
    asm volatile(
        "cp.async.bulk.shared::cta.global.mbarrier::complete_tx::bytes "
        "[%0], [%1], %2, [%3];"
        :: "r"(dst), "l"(src), "r"(bytes), "r"(mbar) : "memory");
}
__device__ __forceinline__ void mbar_wait_parity0(uint32_t mbar) {
    uint32_t done;
    asm volatile(
        "{\n\t.reg .pred p;\n\t"
        "mbarrier.try_wait.parity.acquire.cta.shared::cta.b64 p, [%1], 0;\n\t"
        "selp.b32 %0, 1, 0, p;\n\t}"
        : "=r"(done) : "r"(mbar) : "memory");
    if (!done) {
        asm volatile(
            "{\n\t.reg .pred P1;\n\t"
            "WL_%=:\n\t"
            "mbarrier.try_wait.parity.acquire.cta.shared::cta.b64 P1, [%0], 0, 0x989680;\n\t"
            "@P1 bra.uni WD_%=;\n\t"
            "bra.uni WL_%=;\n\t"
            "WD_%=:\n\t}"
            :: "r"(mbar) : "memory");
    }
}

// ---------------------------------------------------------------------------
// One CTA = 8 rows. Producer (thread 0) streams x-rows + gathered center-rows
// into SMEM via cp.async.bulk (register-free deep MLP); 8 consumer warps each
// reduce one row: ||x - c||^2, clamp, CTA-combine, one atomicAdd per CTA.
// ---------------------------------------------------------------------------
__global__ __launch_bounds__(THREADS, 7)
void center_loss_bulk(const float* __restrict__ x,
                      const void*  __restrict__ labels,
                      const float* __restrict__ centers,
                      float* __restrict__ out)
{
    __shared__ __align__(1024) float s_data[ROWS_PER_CTA * 2 * 512]; // x|c per stage
    __shared__ __align__(8)    unsigned long long s_mbar[ROWS_PER_CTA];
    __shared__ float s_part[ROWS_PER_CTA];

    const int t    = threadIdx.x;
    const int warp = t >> 5;
    const int lane = t & 31;
    const int row0 = blockIdx.x * ROWS_PER_CTA;

    const uint32_t data_base = smem_u32(s_data);
    const uint32_t mbar_base = smem_u32(s_mbar);

    // --- init barriers (count=1: the single expect_tx arrive; flips at 4096B)
    if (t == 0) {
        #pragma unroll
        for (int s = 0; s < ROWS_PER_CTA; s++)
            mbar_init(mbar_base + s * 8, 1);
    }
    __syncthreads();

    // --- producer: thread 0 only -------------------------------------------
    if (t == 0) {
        // x copies first: label-independent, get DRAM going immediately.
        #pragma unroll
        for (int s = 0; s < ROWS_PER_CTA; s++) {
            uint32_t mb = mbar_base + s * 8;
            mbar_expect_tx(mb, 2 * ROW_BYTES);
            bulk_g2s(data_base + s * 2 * ROW_BYTES,
                     x + (size_t)(row0 + s) * D_DIM, ROW_BYTES, mb);
        }

        // labels dtype detect: first 8 u64-interpreted words (64 B; in-bounds
        // for both 8192*i32 and 8192*i64). True i64 labels are < 10000 in
        // every word; packed i32 pairs exceed 2^32 whenever odd label != 0.
        const unsigned long long* lw = (const unsigned long long*)labels;
        bool is64 = true;
        #pragma unroll
        for (int i = 0; i < 8; i++)
            if (lw[i] >= (unsigned long long)C_ROWS) is64 = false;

        long long lbl[ROWS_PER_CTA];
        if (is64) {
            #pragma unroll
            for (int s = 0; s < ROWS_PER_CTA; s++)
                lbl[s] = ((const long long*)labels)[row0 + s];
        } else {
            #pragma unroll
            for (int s = 0; s < ROWS_PER_CTA; s++)
                lbl[s] = (long long)((const int*)labels)[row0 + s];
        }

        // gathered center rows
        #pragma unroll
        for (int s = 0; s < ROWS_PER_CTA; s++) {
            bulk_g2s(data_base + s * 2 * ROW_BYTES + ROW_BYTES,
                     centers + (size_t)lbl[s] * D_DIM, ROW_BYTES,
                     mbar_base + s * 8);
        }
    }

    // --- consumer: warp w processes stage w --------------------------------
    mbar_wait_parity0(mbar_base + warp * 8);

    const float4* xs = reinterpret_cast<const float4*>(
        s_data + warp * 2 * 512);
    const float4* cs = reinterpret_cast<const float4*>(
        s_data + warp * 2 * 512 + 512);

    float acc = 0.0f, d;
    #pragma unroll
    for (int k = 0; k < 4; k++) {
        float4 a = xs[lane + k * 32];
        float4 c = cs[lane + k * 32];
        d = a.x - c.x; acc = fmaf(d, d, acc);
        d = a.y - c.y; acc = fmaf(d, d, acc);
        d = a.z - c.z; acc = fmaf(d, d, acc);
        d = a.w - c.w; acc = fmaf(d, d, acc);
    }

    #pragma unroll
    for (int off = 16; off > 0; off >>= 1)
        acc += __shfl_xor_sync(0xFFFFFFFFu, acc, off);

    if (lane == 0)
        s_part[warp] = fminf(fmaxf(acc, 1e-12f), 1e12f);   // per-row clamp
    __syncthreads();

    if (t == 0) {
        float p = 0.0f;
        #pragma unroll
        for (int w = 0; w < ROWS_PER_CTA; w++) p += s_part[w];
        atomicAdd(out, p * (1.0f / (float)B_ROWS));
    }
}

// ---------------------------------------------------------------------------
// Launch. Inputs identified BY SIZE (robust to metadata ordering):
//   x: 4,194,304 f32 | labels: 8,192 (i32/i64, device-detected) |
//   centers: 5,120,000 f32. Output: scalar f32 (atomic-accumulated).
// ---------------------------------------------------------------------------
extern "C" void kernel_launch(void* const* d_in, const int* in_sizes, int n_in,
                              void* d_out, int out_size)
{
    const float* x       = nullptr;
    const void*  labels  = nullptr;
    const float* centers = nullptr;

    for (int i = 0; i < n_in; i++) {
        if (in_sizes[i] == B_ROWS * D_DIM)       x       = (const float*)d_in[i];
        else if (in_sizes[i] == B_ROWS)          labels  = d_in[i];
        else if (in_sizes[i] == C_ROWS * D_DIM)  centers = (const float*)d_in[i];
    }

    float* out = (float*)d_out;

    cudaMemsetAsync(out, 0, sizeof(float));   // zero accumulator each replay
    center_loss_bulk<<<GRID_CTAS, THREADS>>>(x, labels, centers, out);
}

// round 6
// speedup vs baseline: 1.0198x; 1.0198x over previous
#include <cuda_runtime.h>
#include <cstdint>

#define B_ROWS 8192
#define C_ROWS 10000
#define D_DIM  512
#define ROW_BYTES    2048                  // 512 f32
#define ROWS_PER_CTA 8
#define GRID_CTAS (B_ROWS / ROWS_PER_CTA)  // 1024
#define THREADS 256                        // warp w <-> row/stage w

// Cross-CTA reduction scratch (zero-initialized at load; reset by last CTA).
__device__ float    g_acc;
__device__ unsigned g_count;

__device__ __forceinline__ uint32_t smem_u32(const void* p) {
    uint32_t a;
    asm("{ .reg .u64 t; cvta.to.shared.u64 t, %1; cvt.u32.u64 %0, t; }"
        : "=r"(a) : "l"(p));
    return a;
}
__device__ __forceinline__ void mbar_init(uint32_t mbar, uint32_t count) {
    asm volatile("mbarrier.init.shared.b64 [%0], %1;" :: "r"(mbar), "r"(count) : "memory");
}
__device__ __forceinline__ void mbar_expect_tx(uint32_t mbar, uint32_t bytes) {
    asm volatile("mbarrier.arrive.expect_tx.shared.b64 _, [%0], %1;"
                 :: "r"(mbar), "r"(bytes) : "memory");
}
__device__ __forceinline__ unsigned long long mk_evict_last_policy() {
    unsigned long long pol;
    asm("createpolicy.fractional.L2::evict_last.b64 %0, 1.0;" : "=l"(pol));
    return pol;
}
__device__ __forceinline__ void bulk_g2s(uint32_t dst, const void* src,
                                         uint32_t bytes, uint32_t mbar,
                                         unsigned long long pol) {
    asm volatile(
        "cp.async.bulk.shared::cta.global.mbarrier::complete_tx::bytes.L2::cache_hint "
        "[%0], [%1], %2, [%3], %4;"
        :: "r"(dst), "l"(src), "r"(bytes), "r"(mbar), "l"(pol) : "memory");
}
__device__ __forceinline__ void mbar_wait_parity0(uint32_t mbar) {
    uint32_t done;
    asm volatile(
        "{\n\t.reg .pred p;\n\t"
        "mbarrier.try_wait.parity.acquire.cta.shared::cta.b64 p, [%1], 0;\n\t"
        "selp.b32 %0, 1, 0, p;\n\t}"
        : "=r"(done) : "r"(mbar) : "memory");
    if (!done) {
        asm volatile(
            "{\n\t.reg .pred P1;\n\t"
            "WL_%=:\n\t"
            "mbarrier.try_wait.parity.acquire.cta.shared::cta.b64 P1, [%0], 0, 0x989680;\n\t"
            "@P1 bra.uni WD_%=;\n\t"
            "bra.uni WL_%=;\n\t"
            "WD_%=:\n\t}"
            :: "r"(mbar) : "memory");
    }
}

// ---------------------------------------------------------------------------
// One CTA = 8 rows, one warp per row. Lane 0 of each warp is that row's
// producer: label LDG first (latency overlapped), then bulk x + bulk center
// into this warp's SMEM stage (evict_last so replays stay L2-resident).
// Consumers reduce ||x-c||^2, clamp, CTA-combine; cross-CTA combine via
// g_acc/g_count; LAST CTA writes d_out and resets scratch (no memset node).
// ---------------------------------------------------------------------------
__global__ __launch_bounds__(THREADS, 7)
void center_loss_bulk(const float* __restrict__ x,
                      const void*  __restrict__ labels,
                      const float* __restrict__ centers,
                      float* __restrict__ out)
{
    __shared__ __align__(1024) float s_data[ROWS_PER_CTA * 2 * 512];
    __shared__ __align__(8)    unsigned long long s_mbar[ROWS_PER_CTA];
    __shared__ float s_part[ROWS_PER_CTA];

    const int t    = threadIdx.x;
    const int warp = t >> 5;
    const int lane = t & 31;
    const int row  = blockIdx.x * ROWS_PER_CTA + warp;

    const uint32_t data_base = smem_u32(s_data);
    const uint32_t mb        = smem_u32(s_mbar) + warp * 8;
    const uint32_t stage     = data_base + warp * 2 * ROW_BYTES;

    // ---- issue label-related loads FIRST (latency overlaps everything) ----
    // int32 interpretation: always in-bounds regardless of true dtype.
    int l32 = (lane == 0) ? ((const int*)labels)[row] : 0;
    // dtype-detect words: first 8 u64-interpreted words (64 B, in-bounds for
    // both layouts). True i64 labels < 10000 in every word; packed i32 pairs
    // exceed 2^32 whenever the odd-index label != 0.
    unsigned long long dw = ((const unsigned long long*)labels)[lane & 7];

    // ---- per-warp mbar init + x bulk copy (label-independent) ----
    if (lane == 0) {
        mbar_init(mb, 1);
    }
    __syncwarp();
    unsigned long long pol = mk_evict_last_policy();
    if (lane == 0) {
        mbar_expect_tx(mb, 2 * ROW_BYTES);
        bulk_g2s(stage, x + (size_t)row * D_DIM, ROW_BYTES, mb, pol);
    }

    // ---- resolve label, issue center copy ----
    unsigned big = __ballot_sync(0xFFFFFFFFu, dw >= (unsigned long long)C_ROWS);
    if (lane == 0) {
        long long lbl;
        if (big == 0u)  lbl = ((const long long*)labels)[row];  // true int64
        else            lbl = (long long)l32;                    // int32
        bulk_g2s(stage + ROW_BYTES, centers + (size_t)lbl * D_DIM,
                 ROW_BYTES, mb, pol);
    }

    // ---- consume ----
    mbar_wait_parity0(mb);

    const float4* xs = reinterpret_cast<const float4*>(s_data + warp * 2 * 512);
    const float4* cs = reinterpret_cast<const float4*>(s_data + warp * 2 * 512 + 512);

    float acc = 0.0f, d;
    #pragma unroll
    for (int k = 0; k < 4; k++) {
        float4 a = xs[lane + k * 32];
        float4 c = cs[lane + k * 32];
        d = a.x - c.x; acc = fmaf(d, d, acc);
        d = a.y - c.y; acc = fmaf(d, d, acc);
        d = a.z - c.z; acc = fmaf(d, d, acc);
        d = a.w - c.w; acc = fmaf(d, d, acc);
    }

    #pragma unroll
    for (int off = 16; off > 0; off >>= 1)
        acc += __shfl_xor_sync(0xFFFFFFFFu, acc, off);

    if (lane == 0)
        s_part[warp] = fminf(fmaxf(acc, 1e-12f), 1e12f);   // per-row clamp
    __syncthreads();

    // ---- cross-CTA combine; last CTA writes out + resets scratch ----
    if (t == 0) {
        float p = 0.0f;
        #pragma unroll
        for (int w = 0; w < ROWS_PER_CTA; w++) p += s_part[w];

        atomicAdd(&g_acc, p);
        __threadfence();
        unsigned done = atomicAdd(&g_count, 1u);
        if (done == GRID_CTAS - 1) {
            float total = atomicAdd(&g_acc, 0.0f);         // coherent read
            out[0] = total * (1.0f / (float)B_ROWS);
            atomicExch(&g_acc, 0.0f);                      // reset for next replay
            atomicExch(&g_count, 0u);
        }
    }
}

// ---------------------------------------------------------------------------
// Launch. Inputs identified BY SIZE (robust to metadata ordering):
//   x: 4,194,304 f32 | labels: 8,192 (i32/i64, device-detected) |
//   centers: 5,120,000 f32. Output: scalar f32.
// ---------------------------------------------------------------------------
extern "C" void kernel_launch(void* const* d_in, const int* in_sizes, int n_in,
                              void* d_out, int out_size)
{
    const float* x       = nullptr;
    const void*  labels  = nullptr;
    const float* centers = nullptr;

    for (int i = 0; i < n_in; i++) {
        if (in_sizes[i] == B_ROWS * D_DIM)       x       = (const float*)d_in[i];
        else if (in_sizes[i] == B_ROWS)          labels  = d_in[i];
        else if (in_sizes[i] == C_ROWS * D_DIM)  centers = (const float*)d_in[i];
    }

    float* out = (float*)d_out;
    center_loss_bulk<<<GRID_CTAS, THREADS>>>(x, labels, centers, out);
}

// round 7
// speedup vs baseline: 1.0494x; 1.0291x over previous
#include <cuda_runtime.h>
#include <cstdint>

#define B_ROWS 8192
#define C_ROWS 10000
#define D_DIM  512
#define WARPS_PER_CTA 8
#define GRID_CTAS 512                       // 512 CTAs x 8 warps x 2 rows = 8192
#define ROW_STRIDE 4096                     // second row of each warp

// Cross-CTA scratch (zero-init at module load; last CTA resets each launch).
__device__ float    g_acc;
__device__ unsigned g_count;

// ---------------------------------------------------------------------------
// Fused kernel, 2 rows per warp (identical body to the fastest measured
// kernel), finishing with a fence-free last-CTA reduction.
// ---------------------------------------------------------------------------
__global__ __launch_bounds__(256, 4)
void center_loss_fused(const float* __restrict__ x,
                       const void*  __restrict__ labels,
                       const float* __restrict__ centers,
                       float* __restrict__ out)
{
    __shared__ float s_part[WARPS_PER_CTA];

    const int t    = threadIdx.x;
    const int warp = t >> 5;
    const int lane = t & 31;

    const int gw   = blockIdx.x * WARPS_PER_CTA + warp;  // 0..4095
    const int row0 = gw;
    const int row1 = gw + ROW_STRIDE;

    // ---- issue everything label-independent FIRST ----
    // dtype-detect word (first 8 u64 words: in-bounds for both i32/i64
    // layouts; genuine i64 labels <10000 => every word <10000; packed i32
    // pairs exceed 2^32 whenever the odd-index label != 0).
    unsigned long long dw = ((const unsigned long long*)labels)[lane & 7];
    // int32 interpretation of both labels: ALWAYS in-bounds, load now.
    int l32_0 = ((const int*)labels)[row0];
    int l32_1 = ((const int*)labels)[row1];

    // x loads for both rows: independent of labels, issue all 8 now.
    const float4* __restrict__ xr0 =
        reinterpret_cast<const float4*>(x + (size_t)row0 * D_DIM);
    const float4* __restrict__ xr1 =
        reinterpret_cast<const float4*>(x + (size_t)row1 * D_DIM);
    float4 a00 = xr0[lane];       float4 a01 = xr0[lane + 32];
    float4 a02 = xr0[lane + 64];  float4 a03 = xr0[lane + 96];
    float4 a10 = xr1[lane];       float4 a11 = xr1[lane + 32];
    float4 a12 = xr1[lane + 64];  float4 a13 = xr1[lane + 96];

    // ---- resolve labels ----
    unsigned big = __ballot_sync(0xFFFFFFFFu, dw >= (unsigned long long)C_ROWS);
    long long lbl0, lbl1;
    if (big == 0u) {   // genuine int64 (rare path: one extra dependent load)
        lbl0 = ((const long long*)labels)[row0];
        lbl1 = ((const long long*)labels)[row1];
    } else {           // int32 (already in flight/arrived)
        lbl0 = (long long)l32_0;
        lbl1 = (long long)l32_1;
    }

    const float4* __restrict__ cr0 =
        reinterpret_cast<const float4*>(centers + (size_t)lbl0 * D_DIM);
    const float4* __restrict__ cr1 =
        reinterpret_cast<const float4*>(centers + (size_t)lbl1 * D_DIM);

    // ---- row 0 ----
    float4 c0 = cr0[lane];
    float4 c1 = cr0[lane + 32];
    float4 c2 = cr0[lane + 64];
    float4 c3 = cr0[lane + 96];

    float s0 = 0.0f, d;
    d = a00.x - c0.x; s0 = fmaf(d, d, s0);
    d = a00.y - c0.y; s0 = fmaf(d, d, s0);
    d = a00.z - c0.z; s0 = fmaf(d, d, s0);
    d = a00.w - c0.w; s0 = fmaf(d, d, s0);
    d = a01.x - c1.x; s0 = fmaf(d, d, s0);
    d = a01.y - c1.y; s0 = fmaf(d, d, s0);
    d = a01.z - c1.z; s0 = fmaf(d, d, s0);
    d = a01.w - c1.w; s0 = fmaf(d, d, s0);
    d = a02.x - c2.x; s0 = fmaf(d, d, s0);
    d = a02.y - c2.y; s0 = fmaf(d, d, s0);
    d = a02.z - c2.z; s0 = fmaf(d, d, s0);
    d = a02.w - c2.w; s0 = fmaf(d, d, s0);
    d = a03.x - c3.x; s0 = fmaf(d, d, s0);
    d = a03.y - c3.y; s0 = fmaf(d, d, s0);
    d = a03.z - c3.z; s0 = fmaf(d, d, s0);
    d = a03.w - c3.w; s0 = fmaf(d, d, s0);

    // ---- row 1 ----
    c0 = cr1[lane];
    c1 = cr1[lane + 32];
    c2 = cr1[lane + 64];
    c3 = cr1[lane + 96];

    float s1 = 0.0f;
    d = a10.x - c0.x; s1 = fmaf(d, d, s1);
    d = a10.y - c0.y; s1 = fmaf(d, d, s1);
    d = a10.z - c0.z; s1 = fmaf(d, d, s1);
    d = a10.w - c0.w; s1 = fmaf(d, d, s1);
    d = a11.x - c1.x; s1 = fmaf(d, d, s1);
    d = a11.y - c1.y; s1 = fmaf(d, d, s1);
    d = a11.z - c1.z; s1 = fmaf(d, d, s1);
    d = a11.w - c1.w; s1 = fmaf(d, d, s1);
    d = a12.x - c2.x; s1 = fmaf(d, d, s1);
    d = a12.y - c2.y; s1 = fmaf(d, d, s1);
    d = a12.z - c2.z; s1 = fmaf(d, d, s1);
    d = a12.w - c2.w; s1 = fmaf(d, d, s1);
    d = a13.x - c3.x; s1 = fmaf(d, d, s1);
    d = a13.y - c3.y; s1 = fmaf(d, d, s1);
    d = a13.z - c3.z; s1 = fmaf(d, d, s1);
    d = a13.w - c3.w; s1 = fmaf(d, d, s1);

    // ---- two independent warp reductions (per-row clamp stays separate) ----
    #pragma unroll
    for (int off = 16; off > 0; off >>= 1) {
        s0 += __shfl_xor_sync(0xFFFFFFFFu, s0, off);
        s1 += __shfl_xor_sync(0xFFFFFFFFu, s1, off);
    }

    if (lane == 0) {
        float d0 = fminf(fmaxf(s0, 1e-12f), 1e12f);
        float d1 = fminf(fmaxf(s1, 1e-12f), 1e12f);
        s_part[warp] = d0 + d1;
    }
    __syncthreads();

    // ---- fence-free cross-CTA finish (no memset graph node needed) ----
    if (t == 0) {
        float p = 0.0f;
        #pragma unroll
        for (int w = 0; w < WARPS_PER_CTA; w++) p += s_part[w];
        p *= (1.0f / (float)B_ROWS);

        // Accumulate partial (relaxed atomic; L2-resident, bypasses L1).
        asm volatile("red.global.add.f32 [%0], %1;"
                     :: "l"(&g_acc), "f"(p) : "memory");
        // Release-increment the counter: orders the red above before it.
        unsigned prev;
        asm volatile("atom.release.gpu.global.add.u32 %0, [%1], 1;"
                     : "=r"(prev) : "l"(&g_count) : "memory");
        if (prev == GRID_CTAS - 1) {
            // Acquire-read the accumulator: sees every CTA's release-ordered red.
            float total;
            asm volatile("ld.acquire.gpu.global.f32 %0, [%1];"
                         : "=f"(total) : "l"(&g_acc) : "memory");
            out[0] = total;
            g_acc   = 0.0f;     // reset for next replay (kernel-boundary fenced)
            g_count = 0u;
        }
    }
}

// ---------------------------------------------------------------------------
// Launch. Inputs identified BY SIZE (robust to metadata ordering):
//   x: 4,194,304 f32 | labels: 8,192 (i32/i64, device-detected) |
//   centers: 5,120,000 f32. Output: scalar f32.
// ---------------------------------------------------------------------------
extern "C" void kernel_launch(void* const* d_in, const int* in_sizes, int n_in,
                              void* d_out, int out_size)
{
    const float* x       = nullptr;
    const void*  labels  = nullptr;
    const float* centers = nullptr;

    for (int i = 0; i < n_in; i++) {
        if (in_sizes[i] == B_ROWS * D_DIM)       x       = (const float*)d_in[i];
        else if (in_sizes[i] == B_ROWS)          labels  = d_in[i];
        else if (in_sizes[i] == C_ROWS * D_DIM)  centers = (const float*)d_in[i];
    }

    float* out = (float*)d_out;
    center_loss_fused<<<GRID_CTAS, 32 * WARPS_PER_CTA>>>(x, labels, centers, out);
}